// round 14
// baseline (speedup 1.0000x reference)
#include <cuda_runtime.h>

// FeatureSim: attn[b,i,j] = softmax_j( sum_k w[k]*|x[b,i,k]-x[b,j,k]| ), mask j < len[b].
// B=8, L=1024, F=16 (first 11 used), out f32 [8,1024,1024].
//
// R14: R13 (19.0us) + feature-major key layout.
//      R13's remaining L1 hog: key LDGs = 192 of ~310 wf/warp (row-major x forces
//      64B lane stride -> 16 wf/inst). A tiny prologue kernel transposes x into
//      xT[b][k][j] (__device__ scratch, sanctioned). Key loads become fully
//      coalesced scalar LDGs: 44 x 1 wf = 44 wf/warp. L1 stops binding; the
//      FFMA pipe (704 fma-class instrs/thread) becomes the floor.
//      Main kernel otherwise identical to R13: strided 4-col ownership, scalar
//      FADD/FFMA core (free |.|/-), ex2.approx, -1e30 mask bias, e-slab once,
//      fused warp-per-row epilogue, 2 barriers, 3 blocks/SM.

#define L_SEQ 1024
#define FDIM  16
#define NF    11
#define BQ    8             // rows per block == warps per block
#define TPB   256
#define BPB   (L_SEQ / BQ)  // 128 blocks per batch
#define CSTRIDE (L_SEQ / 4) // 256: column stride between a thread's 4 cols

__device__ float g_xT[8][12][L_SEQ];   // feature-major copy of x (k<11 used), 384KB

__device__ __forceinline__ float ex2(float a) {
    float r; asm("ex2.approx.f32 %0, %1;" : "=f"(r) : "f"(a)); return r;
}

#define LOG2E 1.4426950408889634f

// ---------------- Prologue: x[b][j][k] -> g_xT[b][k][j] ----------------
// 32 blocks: (batch b, 256-row chunk). Coalesced LDG via smem tile, coalesced STG.
__global__ __launch_bounds__(TPB)
void transpose_kernel(const float* __restrict__ x)
{
    const int b     = blockIdx.x >> 2;          // 0..7
    const int chunk = blockIdx.x & 3;           // 0..3 (256 rows each)
    const int t     = threadIdx.x;

    __shared__ float ts[256][17];               // pad 17: conflict-free both phases

    // Load 256 rows x 16 floats = 1024 float4, fully coalesced.
    const float4* xb = reinterpret_cast<const float4*>(
        x + (size_t)(b * L_SEQ + chunk * 256) * FDIM);
#pragma unroll
    for (int i = 0; i < 4; ++i) {
        int f   = t + i * 256;                  // float4 index in chunk
        int row = f >> 2, quad = f & 3;
        float4 v = xb[f];
        ts[row][quad * 4 + 0] = v.x;
        ts[row][quad * 4 + 1] = v.y;
        ts[row][quad * 4 + 2] = v.z;
        ts[row][quad * 4 + 3] = v.w;
    }
    __syncthreads();

    // Write k-major, coalesced over j.
#pragma unroll
    for (int k = 0; k < NF; ++k)
        g_xT[b][k][chunk * 256 + t] = ts[t][k];
}

// ---------------- Main kernel ----------------
__global__ __launch_bounds__(TPB, 3)
void featsim_kernel(const float* __restrict__ x,
                    const int*   __restrict__ lens,
                    const float* __restrict__ w,
                    float*       __restrict__ out)
{
    const int b    = blockIdx.x / BPB;
    const int rb   = blockIdx.x % BPB;
    const int i0   = rb * BQ;
    const int tid  = threadIdx.x;
    const int lane = tid & 31;
    const int warp = tid >> 5;          // 0..7; warp w owns row w in the epilogue

    __shared__ __align__(16) float sq[BQ][12];      // raw queries (11 used, pad 0)
    __shared__ __align__(16) float se[BQ][L_SEQ];   // unnormalized e staging (32 KB)

    // Signed per-feature scale wl_k = w_k * log2e (|d| via free abs modifier).
    float wl[NF];
#pragma unroll
    for (int k = 0; k < NF; ++k) wl[k] = w[k] * LOG2E;

    // Stage raw queries (from row-major x; tiny).
    if (tid < BQ * 12) {
        int r = tid / 12, k = tid - r * 12;
        sq[r][k] = (k < NF) ? x[(size_t)(b * L_SEQ + i0 + r) * FDIM + k] : 0.f;
    }

    // Keys from feature-major xT: lane stride 4B -> every LDG is 1 wavefront.
    float kk[4][NF];
#pragma unroll
    for (int k = 0; k < NF; ++k) {
        const float* kp = &g_xT[b][k][tid];
#pragma unroll
        for (int cc = 0; cc < 4; ++cc)
            kk[cc][k] = kp[cc * CSTRIDE];
    }

    // Key-mask as accumulator bias: invalid col -> -1e30 -> ex2 -> exact 0.
    const int len = lens[b];
    float bias[4];
#pragma unroll
    for (int cc = 0; cc < 4; ++cc)
        bias[cc] = (tid + CSTRIDE * cc < len) ? 0.f : -1e30f;

    __syncthreads();

    // ---- compute: 3 LDS.128/row + 88 FADD/FFMA + 4 ex2 + 4 STS.32 ----
#pragma unroll
    for (int r = 0; r < BQ; ++r) {
        const float4* qp = reinterpret_cast<const float4*>(sq[r]);
        float4 qa = qp[0];              // features 0..3
        float4 qb = qp[1];              // features 4..7
        float4 qc = qp[2];              // features 8..10 (+pad)
        const float qs[NF] = { qa.x, qa.y, qa.z, qa.w,
                               qb.x, qb.y, qb.z, qb.w,
                               qc.x, qc.y, qc.z };

        float s0 = bias[0], s1 = bias[1], s2 = bias[2], s3 = bias[3];
#pragma unroll
        for (int k = 0; k < NF; ++k) {
            const float q = qs[k], wk = wl[k];
            s0 = fmaf(fabsf(q - kk[0][k]), wk, s0);
            s1 = fmaf(fabsf(q - kk[1][k]), wk, s1);
            s2 = fmaf(fabsf(q - kk[2][k]), wk, s2);
            s3 = fmaf(fabsf(q - kk[3][k]), wk, s3);
        }

        se[r][tid + 0 * CSTRIDE] = ex2(s0);
        se[r][tid + 1 * CSTRIDE] = ex2(s1);
        se[r][tid + 2 * CSTRIDE] = ex2(s2);
        se[r][tid + 3 * CSTRIDE] = ex2(s3);
    }
    __syncthreads();

    // ---- fused reduce + normalize + store: warp w owns row w ----
    {
        float4 v[8];
        float acc = 0.f;
#pragma unroll
        for (int p = 0; p < 8; ++p) {
            v[p] = *reinterpret_cast<float4*>(&se[warp][lane * 4 + p * 128]);
            acc += (v[p].x + v[p].y) + (v[p].z + v[p].w);
        }
#pragma unroll
        for (int o = 16; o > 0; o >>= 1)
            acc += __shfl_xor_sync(0xffffffffu, acc, o);

        float inv; asm("rcp.approx.f32 %0, %1;" : "=f"(inv) : "f"(acc));  // len>=1 => acc>0

        float4* orow = reinterpret_cast<float4*>(
            out + (size_t)(b * L_SEQ + i0 + warp) * L_SEQ);
#pragma unroll
        for (int p = 0; p < 8; ++p) {
            orow[p * 32 + lane] =
                make_float4(v[p].x * inv, v[p].y * inv, v[p].z * inv, v[p].w * inv);
        }
    }
}

extern "C" void kernel_launch(void* const* d_in, const int* in_sizes, int n_in,
                              void* d_out, int out_size)
{
    const float* x    = (const float*)d_in[0];   // [8,1024,16] f32
    const int*   lens = (const int*)d_in[1];     // [8] i32
    const float* w    = (const float*)d_in[2];   // [11] f32
    float*       out  = (float*)d_out;           // [8,1024,1024] f32

    transpose_kernel<<<32, TPB>>>(x);            // x -> g_xT (feature-major)
    featsim_kernel<<<8 * BPB, TPB>>>(x, lens, w, out);   // 1024 blocks
}